// round 10
// baseline (speedup 1.0000x reference)
#include <cuda_runtime.h>
#include <cuda_bf16.h>
#include <cstdint>
#include <math.h>

// Problem shape (fixed): B=16, T=S=E=D=1024
#define B_  16
#define T_  1024
#define S_  1024
#define E_  1024
#define D_  1024

#define BT_   (B_ * T_)          // 16384
#define BS_   (B_ * S_)          // 16384
#define OUT1  (BT_ * D_)
#define OUT2  (BT_ * S_)

// word counts (1 word = 2 elements packed bf16x2)
#define HID_W  (BT_ * D_ / 2)          // 8M words
#define ENC_W  (BS_ * E_ / 2)
#define WAT_W  (D_ * E_ / 2)
#define WOUT_W (D_ * (E_ + D_) / 2)

// Device-global scratch (cudaMalloc forbidden). All operands pre-split into
// hi/lo bf16x2 word arrays (word i = elements 2i,2i+1; elem 2i in lower half).
__device__ uint32_t g_hid_hi [HID_W],  g_hid_lo [HID_W];
__device__ uint32_t g_enc_hi [ENC_W],  g_enc_lo [ENC_W];
__device__ uint32_t g_wat_hi [WAT_W],  g_wat_lo [WAT_W];
__device__ uint32_t g_wout_hi[WOUT_W], g_wout_lo[WOUT_W];
__device__ uint32_t g_proj_hi[ENC_W],  g_proj_lo[ENC_W];    // (B,S,D)
__device__ uint32_t g_encT_hi[ENC_W],  g_encT_lo[ENC_W];    // (B,E,S)
__device__ uint32_t g_wts_hi[OUT2/2],  g_wts_lo[OUT2/2];    // (B,T,S)
__device__ uint32_t g_wc_hi [HID_W],   g_wc_lo [HID_W];     // (B,T,E)

// ---------------------------------------------------------------------------
// helpers (baseline PTX only — compiles at family target sm_103)
// ---------------------------------------------------------------------------
__device__ __forceinline__ uint32_t smem_u32(const void* p) {
    uint32_t a;
    asm("{ .reg .u64 t; cvta.to.shared.u64 t, %1; cvt.u32.u64 %0, t; }"
        : "=r"(a) : "l"(p));
    return a;
}
// packs {upper = bf16(hf), lower = bf16(lf)}
__device__ __forceinline__ uint32_t pack_bf16x2(float hf, float lf) {
    uint32_t r;
    asm("cvt.rn.bf16x2.f32 %0, %1, %2;" : "=r"(r) : "f"(hf), "f"(lf));
    return r;
}
// split pair (x = elem 2i, y = elem 2i+1) -> hi word, lo (residual) word
__device__ __forceinline__ void split2(float x, float y, uint32_t& hw, uint32_t& lw) {
    hw = pack_bf16x2(y, x);
    float rx = x - __uint_as_float(hw << 16);
    float ry = y - __uint_as_float(hw & 0xFFFF0000u);
    lw = pack_bf16x2(ry, rx);
}
__device__ __forceinline__ void mma16(float* d, const uint32_t* a, const uint32_t* b) {
    asm volatile(
        "mma.sync.aligned.m16n8k16.row.col.f32.bf16.bf16.f32 "
        "{%0,%1,%2,%3}, {%4,%5,%6,%7}, {%8,%9}, {%0,%1,%2,%3};"
        : "+f"(d[0]), "+f"(d[1]), "+f"(d[2]), "+f"(d[3])
        : "r"(a[0]), "r"(a[1]), "r"(a[2]), "r"(a[3]), "r"(b[0]), "r"(b[1]));
}
__device__ __forceinline__ void ldsm4(uint32_t* r, uint32_t saddr) {
    asm volatile("ldmatrix.sync.aligned.m8n8.x4.shared.b16 {%0,%1,%2,%3}, [%4];"
        : "=r"(r[0]), "=r"(r[1]), "=r"(r[2]), "=r"(r[3]) : "r"(saddr));
}

// ---------------------------------------------------------------------------
// SMEM layout (32-bit words) — same as R9, proven conflict-free:
// per operand per stage: 4 subtiles u (k = 8u..8u+7), each [128 rows][8 words],
// row stride 12 words, subtile stride KSS. Row segment: words 0-3 = hi pairs,
// words 4-7 = lo pairs. ldmatrix 8-row phases hit banks {12r mod 32} -> all 32.
// ---------------------------------------------------------------------------
#define KSS      1544
#define AREG     (4 * KSS)            // 6176 words per operand per stage
#define STAGEF   (2 * AREG)           // words per stage (A|B)
#define GEMM_SMEM (2 * STAGEF * 4)    // 98816 bytes, double buffered

// ---------------------------------------------------------------------------
// split-bf16 tensor-core GEMM on pre-split operands.
// C[m,n] = ep( sum_k A[m,k]*B[n,k] (+bias[n]) ),  acc += Ah*Bh + Ah*Bl + Al*Bh
// Tile 128x128x32, 256 threads (8 warps, 2x4), warp tile 64x32.
// OUT_F32: write float C. OUT_SPLIT: write hi/lo bf16x2 word arrays.
// ---------------------------------------------------------------------------
template<bool DUAL_A, bool BIAS, bool TANH_EP, bool OUT_F32, bool OUT_SPLIT>
__global__ __launch_bounds__(256, 1)
void gemm_mma(const uint32_t* __restrict__ A0h, const uint32_t* __restrict__ A0l,
              const uint32_t* __restrict__ A1h, const uint32_t* __restrict__ A1l,
              const uint32_t* __restrict__ Bh,  const uint32_t* __restrict__ Bl,
              const float* __restrict__ bias,
              float* __restrict__ C,
              uint32_t* __restrict__ Chi, uint32_t* __restrict__ Clo,
              int K, int Ksplit, int ldaw, int ldbw, int ldc,
              long long sAw, long long sBw, long long sC)
{
    extern __shared__ uint32_t sm[];
    const uint32_t sbase = smem_u32(sm);
    const int tid  = threadIdx.x;
    const int lane = tid & 31;
    const int wid  = tid >> 5;
    const int g = lane >> 2, t = lane & 3;
    const int warp_m = wid & 1;
    const int warp_n = wid >> 1;

    const int bz = blockIdx.z;
    const int bm = blockIdx.y * 128;
    const int bn = blockIdx.x * 128;

    const uint32_t* a0h = A0h + bz * sAw;
    const uint32_t* a0l = A0l + bz * sAw;
    const uint32_t* a1h = DUAL_A ? (A1h + bz * sAw) : nullptr;
    const uint32_t* a1l = DUAL_A ? (A1l + bz * sAw) : nullptr;
    const uint32_t* bhp = Bh + bz * sBw;
    const uint32_t* blp = Bl + bz * sBw;

    // staging indices: thread (row0, c4): subtile u = c4&3, array sel = c4>>2
    const int row0 = tid >> 3;            // 0..31
    const int c4   = tid & 7;
    const int u    = c4 & 3;
    const int isLo = c4 >> 2;
    const int sts_woff = row0 * 12 + u * KSS + isLo * 4;
    const uint32_t* Bsrc = isLo ? blp : bhp;

    // ldmatrix per-lane bases (word offsets)
    const int q = lane >> 3, rIn = lane & 7;
    const int a_lm = (warp_m * 64 + (q & 1) * 8 + rIn) * 12 + (q >> 1) * KSS;
    const int b_lm = AREG + (warp_n * 32 + (q >> 1) * 8 + rIn) * 12 + (q & 1) * KSS;

    float acc[4][4][4];
#pragma unroll
    for (int i = 0; i < 4; i++)
#pragma unroll
        for (int j = 0; j < 4; j++)
#pragma unroll
            for (int c = 0; c < 4; c++) acc[i][j][c] = 0.f;

    const int nstages = K >> 5;

    // --- stage 0 preload ---
    {
        const uint32_t* Asrc = isLo ? a0l : a0h;
        if (DUAL_A && 0 >= Ksplit) Asrc = isLo ? a1l : a1h;
        uint4 pa[4], pb[4];
#pragma unroll
        for (int r = 0; r < 4; r++) {
            pa[r] = *(const uint4*)(Asrc + (long long)(bm + row0 + 32 * r) * ldaw + u * 4);
            pb[r] = *(const uint4*)(Bsrc + (long long)(bn + row0 + 32 * r) * ldbw + u * 4);
        }
#pragma unroll
        for (int r = 0; r < 4; r++) {
            *(uint4*)(sm + sts_woff + 384 * r)        = pa[r];
            *(uint4*)(sm + AREG + sts_woff + 384 * r) = pb[r];
        }
        __syncthreads();
    }

    for (int s = 0; s < nstages; ++s) {
        uint4 pa[4], pb[4];
        const bool more = (s + 1 < nstages);
        if (more) {
            const int k0 = (s + 1) << 5;
            const uint32_t* Ah_; const uint32_t* Al_; int klw;
            if (DUAL_A && k0 >= Ksplit) { Ah_ = a1h; Al_ = a1l; klw = (k0 - Ksplit) >> 1; }
            else                        { Ah_ = a0h; Al_ = a0l; klw = k0 >> 1; }
            const uint32_t* Asrc = isLo ? Al_ : Ah_;
            const int k0w = k0 >> 1;
#pragma unroll
            for (int r = 0; r < 4; r++) {
                pa[r] = *(const uint4*)(Asrc + (long long)(bm + row0 + 32 * r) * ldaw + klw + u * 4);
                pb[r] = *(const uint4*)(Bsrc + (long long)(bn + row0 + 32 * r) * ldbw + k0w + u * 4);
            }
        }

        // ---- compute current stage: 2 k-chunks of 16 ----
        const uint32_t stg = sbase + ((s & 1) * STAGEF) * 4;
#pragma unroll
        for (int kc = 0; kc < 2; kc++) {
            const int kcw = kc * 2 * KSS;
            uint32_t ah[4][4], al[4][4], bh[4][2], bl[4][2];
#pragma unroll
            for (int i = 0; i < 4; i++) {
                ldsm4(ah[i], stg + (uint32_t)(a_lm + i * 192 + kcw) * 4);
                ldsm4(al[i], stg + (uint32_t)(a_lm + i * 192 + kcw + 4) * 4);
            }
#pragma unroll
            for (int jp = 0; jp < 2; jp++) {
                uint32_t rr[4];
                ldsm4(rr, stg + (uint32_t)(b_lm + jp * 192 + kcw) * 4);
                bh[2 * jp][0] = rr[0]; bh[2 * jp][1] = rr[1];
                bh[2 * jp + 1][0] = rr[2]; bh[2 * jp + 1][1] = rr[3];
                ldsm4(rr, stg + (uint32_t)(b_lm + jp * 192 + kcw + 4) * 4);
                bl[2 * jp][0] = rr[0]; bl[2 * jp][1] = rr[1];
                bl[2 * jp + 1][0] = rr[2]; bl[2 * jp + 1][1] = rr[3];
            }
#pragma unroll
            for (int i = 0; i < 4; i++)
#pragma unroll
                for (int j = 0; j < 4; j++) {
                    mma16(acc[i][j], ah[i], bh[j]);
                    mma16(acc[i][j], ah[i], bl[j]);
                    mma16(acc[i][j], al[i], bh[j]);
                }
        }

        if (more) {
            uint32_t* nb = sm + ((s + 1) & 1) * STAGEF;
#pragma unroll
            for (int r = 0; r < 4; r++) {
                *(uint4*)(nb + sts_woff + 384 * r)        = pa[r];
                *(uint4*)(nb + AREG + sts_woff + 384 * r) = pb[r];
            }
        }
        __syncthreads();
    }

    // ---- epilogue ----
    float* cp = OUT_F32 ? (C + bz * sC) : nullptr;
    uint32_t* chi = OUT_SPLIT ? (Chi + bz * (sC >> 1)) : nullptr;
    uint32_t* clo = OUT_SPLIT ? (Clo + bz * (sC >> 1)) : nullptr;
    const int ldcw = ldc >> 1;
#pragma unroll
    for (int i = 0; i < 4; i++) {
#pragma unroll
        for (int h = 0; h < 2; h++) {
            const int m = bm + warp_m * 64 + i * 16 + g + h * 8;
#pragma unroll
            for (int j = 0; j < 4; j++) {
                const int n = bn + warp_n * 32 + j * 8 + t * 2;
                float x = acc[i][j][h * 2];
                float y = acc[i][j][h * 2 + 1];
                if (BIAS)    { x += __ldg(bias + n); y += __ldg(bias + n + 1); }
                if (TANH_EP) { x = tanhf(x);         y = tanhf(y); }
                if (OUT_F32)
                    *(float2*)(cp + (long long)m * ldc + n) = make_float2(x, y);
                if (OUT_SPLIT) {
                    uint32_t hw, lw;
                    split2(x, y, hw, lw);
                    long long w = (long long)m * ldcw + (n >> 1);
                    chi[w] = hw; clo[w] = lw;
                }
            }
        }
    }
}

// ---------------------------------------------------------------------------
// Elementwise f32 -> hi/lo bf16x2 split (4 elements / thread)
// ---------------------------------------------------------------------------
__global__ __launch_bounds__(256)
void split_pairs(const float* __restrict__ x, uint32_t* __restrict__ hi,
                 uint32_t* __restrict__ lo, int n4)
{
    int i = blockIdx.x * blockDim.x + threadIdx.x;
    if (i >= n4) return;
    float4 v = ((const float4*)x)[i];
    uint32_t h0, l0, h1, l1;
    split2(v.x, v.y, h0, l0);
    split2(v.z, v.w, h1, l1);
    ((uint2*)hi)[i] = make_uint2(h0, h1);
    ((uint2*)lo)[i] = make_uint2(l0, l1);
}

// ---------------------------------------------------------------------------
// enc (B,S,E) f32 -> encT (B,E,S) pre-split hi/lo words
// ---------------------------------------------------------------------------
__global__ __launch_bounds__(256)
void transpose_split(const float* __restrict__ in,
                     uint32_t* __restrict__ thi, uint32_t* __restrict__ tlo)
{
    __shared__ float tb[32][33];
    const int b = blockIdx.z;
    const int s0 = blockIdx.x * 32, e0 = blockIdx.y * 32;
    const float* ip = in + (long long)b * S_ * E_;
    const int tx = threadIdx.x, ty = threadIdx.y;
#pragma unroll
    for (int r = ty; r < 32; r += 8)
        tb[r][tx] = ip[(long long)(s0 + r) * E_ + e0 + tx];
    __syncthreads();

    const int w = tx & 15, half = tx >> 4;
    const long long base = (long long)b * (E_ * S_ / 2);
#pragma unroll
    for (int ro = 0; ro < 2; ro++) {
        const int e = ro * 16 + half * 8 + ty;   // 0..31
        uint32_t h, l;
        split2(tb[2 * w][e], tb[2 * w + 1][e], h, l);
        long long widx = base + (long long)(e0 + e) * (S_ / 2) + (s0 >> 1) + w;
        thi[widx] = h; tlo[widx] = l;
    }
}

// ---------------------------------------------------------------------------
// Row softmax over S=1024; writes f32 weights + pre-split hi/lo words
// ---------------------------------------------------------------------------
__global__ __launch_bounds__(256)
void softmax_split(const float* __restrict__ in, float* __restrict__ outw,
                   uint32_t* __restrict__ whi, uint32_t* __restrict__ wlo)
{
    const long long row = blockIdx.x;
    const float* x = in   + row * 1024;
    float*       y = outw + row * 1024;
    const int tid = threadIdx.x, lane = tid & 31, warp = tid >> 5;
    __shared__ float redmax[8], redsum[8];

    float4 v = ((const float4*)x)[tid];
    float mx = fmaxf(fmaxf(v.x, v.y), fmaxf(v.z, v.w));
#pragma unroll
    for (int o = 16; o; o >>= 1) mx = fmaxf(mx, __shfl_xor_sync(~0u, mx, o));
    if (lane == 0) redmax[warp] = mx;
    __syncthreads();
    mx = redmax[0];
#pragma unroll
    for (int w = 1; w < 8; w++) mx = fmaxf(mx, redmax[w]);

    float e0 = __expf(v.x - mx), e1 = __expf(v.y - mx);
    float e2 = __expf(v.z - mx), e3 = __expf(v.w - mx);
    float s = (e0 + e1) + (e2 + e3);
#pragma unroll
    for (int o = 16; o; o >>= 1) s += __shfl_xor_sync(~0u, s, o);
    if (lane == 0) redsum[warp] = s;
    __syncthreads();
    s = redsum[0];
#pragma unroll
    for (int w = 1; w < 8; w++) s += redsum[w];

    const float inv = 1.f / s;
    float4 o4 = make_float4(e0 * inv, e1 * inv, e2 * inv, e3 * inv);
    ((float4*)y)[tid] = o4;

    uint32_t h0, l0, h1, l1;
    split2(o4.x, o4.y, h0, l0);
    split2(o4.z, o4.w, h1, l1);
    const long long wbase = row * 512 + 2 * tid;
    *(uint2*)(whi + wbase) = make_uint2(h0, h1);
    *(uint2*)(wlo + wbase) = make_uint2(l0, l1);
}

// ---------------------------------------------------------------------------
// Launcher
// ---------------------------------------------------------------------------
extern "C" void kernel_launch(void* const* d_in, const int* in_sizes, int n_in,
                              void* d_out, int out_size)
{
    const float* hidden = (const float*)d_in[0];
    const float* enc    = (const float*)d_in[1];
    const float* W_attn = (const float*)d_in[2];
    const float* b_attn = (const float*)d_in[3];
    const float* W_out  = (const float*)d_in[4];

    float* out      = (float*)d_out;
    float* h_tilde  = out;
    float* weights  = out + OUT1;
    float* energies = out + OUT1 + OUT2;

    uint32_t *hid_hi, *hid_lo, *enc_hi, *enc_lo, *wat_hi, *wat_lo,
             *wout_hi, *wout_lo, *proj_hi, *proj_lo, *encT_hi, *encT_lo,
             *wts_hi, *wts_lo, *wc_hi, *wc_lo;
    cudaGetSymbolAddress((void**)&hid_hi,  g_hid_hi);
    cudaGetSymbolAddress((void**)&hid_lo,  g_hid_lo);
    cudaGetSymbolAddress((void**)&enc_hi,  g_enc_hi);
    cudaGetSymbolAddress((void**)&enc_lo,  g_enc_lo);
    cudaGetSymbolAddress((void**)&wat_hi,  g_wat_hi);
    cudaGetSymbolAddress((void**)&wat_lo,  g_wat_lo);
    cudaGetSymbolAddress((void**)&wout_hi, g_wout_hi);
    cudaGetSymbolAddress((void**)&wout_lo, g_wout_lo);
    cudaGetSymbolAddress((void**)&proj_hi, g_proj_hi);
    cudaGetSymbolAddress((void**)&proj_lo, g_proj_lo);
    cudaGetSymbolAddress((void**)&encT_hi, g_encT_hi);
    cudaGetSymbolAddress((void**)&encT_lo, g_encT_lo);
    cudaGetSymbolAddress((void**)&wts_hi,  g_wts_hi);
    cudaGetSymbolAddress((void**)&wts_lo,  g_wts_lo);
    cudaGetSymbolAddress((void**)&wc_hi,   g_wc_hi);
    cudaGetSymbolAddress((void**)&wc_lo,   g_wc_lo);

    cudaFuncSetAttribute(gemm_mma<false, true,  false, false, true >,
        cudaFuncAttributeMaxDynamicSharedMemorySize, GEMM_SMEM);
    cudaFuncSetAttribute(gemm_mma<false, false, false, true,  false>,
        cudaFuncAttributeMaxDynamicSharedMemorySize, GEMM_SMEM);
    cudaFuncSetAttribute(gemm_mma<false, false, false, false, true >,
        cudaFuncAttributeMaxDynamicSharedMemorySize, GEMM_SMEM);
    cudaFuncSetAttribute(gemm_mma<true,  false, true,  true,  false>,
        cudaFuncAttributeMaxDynamicSharedMemorySize, GEMM_SMEM);

    // Pre-split inputs (hi/lo bf16x2 word arrays)
    split_pairs<<<(BT_ * D_ / 4 + 255) / 256, 256>>>(hidden, hid_hi, hid_lo, BT_ * D_ / 4);
    split_pairs<<<(BS_ * E_ / 4 + 255) / 256, 256>>>(enc, enc_hi, enc_lo, BS_ * E_ / 4);
    split_pairs<<<(D_ * E_ / 4 + 255) / 256, 256>>>(W_attn, wat_hi, wat_lo, D_ * E_ / 4);
    split_pairs<<<(D_ * (E_ + D_) / 4 + 255) / 256, 256>>>(W_out, wout_hi, wout_lo,
                                                           D_ * (E_ + D_) / 4);
    // enc -> encT (pre-split, consumed by GEMM 3)
    transpose_split<<<dim3(S_ / 32, E_ / 32, B_), dim3(32, 8)>>>(enc, encT_hi, encT_lo);

    // 1) proj = enc @ W_attn^T + b : M=16384, N=1024, K=1024 -> split out
    gemm_mma<false, true, false, false, true>
        <<<dim3(D_ / 128, BS_ / 128, 1), 256, GEMM_SMEM>>>(
        enc_hi, enc_lo, nullptr, nullptr, wat_hi, wat_lo, b_attn,
        nullptr, proj_hi, proj_lo,
        E_, 0, E_ / 2, E_ / 2, D_, 0, 0, 0);

    // 2) energies[b] = hidden[b] @ proj[b]^T : batched M=N=K=1024 -> f32
    gemm_mma<false, false, false, true, false>
        <<<dim3(S_ / 128, T_ / 128, B_), 256, GEMM_SMEM>>>(
        hid_hi, hid_lo, nullptr, nullptr, proj_hi, proj_lo, nullptr,
        energies, nullptr, nullptr,
        D_, 0, D_ / 2, D_ / 2, S_,
        (long long)T_ * D_ / 2, (long long)S_ * D_ / 2, (long long)T_ * S_);

    // 3) softmax (+ split weights)
    softmax_split<<<BT_, 256>>>(energies, weights, wts_hi, wts_lo);

    // 4) wc[b] = weights[b] @ encT[b]^T : batched M=N=K=1024 -> split out
    gemm_mma<false, false, false, false, true>
        <<<dim3(E_ / 128, T_ / 128, B_), 256, GEMM_SMEM>>>(
        wts_hi, wts_lo, nullptr, nullptr, encT_hi, encT_lo, nullptr,
        nullptr, wc_hi, wc_lo,
        S_, 0, S_ / 2, S_ / 2, E_,
        (long long)T_ * S_ / 2, (long long)E_ * S_ / 2, (long long)T_ * E_);

    // 5) h_tilde = tanh([wc|hidden] @ W_out^T) : M=16384, N=1024, K=2048
    gemm_mma<true, false, true, true, false>
        <<<dim3(D_ / 128, BT_ / 128, 1), 256, GEMM_SMEM>>>(
        wc_hi, wc_lo, hid_hi, hid_lo, wout_hi, wout_lo, nullptr,
        h_tilde, nullptr, nullptr,
        E_ + D_, E_, E_ / 2, (E_ + D_) / 2, D_, 0, 0, 0);

    (void)in_sizes; (void)n_in; (void)out_size;
}